// round 15
// baseline (speedup 1.0000x reference)
#include <cuda_runtime.h>

#define BB 8
#define PP 12000
#define NP (BB*PP)
#define XN_ 144
#define CELLS (144*144)
#define NC (BB*CELLS)
#define NBLK 456
#define NWARPS (NBLK*8)

#define ROW 10     // float2 stride per m-row (9 used + 1 pad)
#define HALF 161   // float2 offset of the mg=1 half (16*ROW+1: bank-shifts halves)
#define BUFSZ 330  // HALF + 15*ROW + 9 + pad

// per-(batch,cell) winning pillar index (last write wins == max p)
__device__ int  g_winner[NC];
__device__ int  g_count;
__device__ int2 g_list[NP];      // (pillar id, out-base = b*64*CELLS + flat)

__global__ void k_winner(const int* __restrict__ idx) {
    int i = blockIdx.x * blockDim.x + threadIdx.x;   // grid sized exactly NP
    int y = idx[i * 3 + 1];
    int x = idx[i * 3 + 2];
    x = min(max(x, 0), 143);
    y = min(max(y, 0), 143);
    int b = i / PP;
    int p = i - b * PP;
    atomicMax(&g_winner[b * CELLS + y * XN_ + x], p);
}

// Compact winners into g_list (warp-aggregated atomic: 1 atomicAdd per warp).
__global__ void k_collect(const int* __restrict__ idx) {
    int i = blockIdx.x * blockDim.x + threadIdx.x;
    int lane = threadIdx.x & 31;
    int y = idx[i * 3 + 1];
    int x = idx[i * 3 + 2];
    x = min(max(x, 0), 143);
    y = min(max(y, 0), 143);
    int b = i / PP;
    int p = i - b * PP;
    int flat = y * XN_ + x;
    bool win = (g_winner[b * CELLS + flat] == p);
    unsigned m = __ballot_sync(0xFFFFFFFFu, win);
    int base = 0;
    if (lane == 0 && m) base = atomicAdd(&g_count, __popc(m));
    base = __shfl_sync(0xFFFFFFFFu, base, 0);
    if (win) {
        int pos = base + __popc(m & ((1u << lane) - 1u));
        g_list[pos] = make_int2(i, b * 64 * CELLS + flat);
    }
}

__device__ __forceinline__ unsigned long long fma2(unsigned long long a,
                                                   unsigned long long b,
                                                   unsigned long long c) {
    unsigned long long d;
    asm("fma.rn.f32x2 %0, %1, %2, %3;" : "=l"(d) : "l"(a), "l"(b), "l"(c));
    return d;
}
__device__ __forceinline__ unsigned long long pack2(float lo, float hi) {
    unsigned long long d;
    asm("mov.b64 %0, {%1, %2};" : "=l"(d) : "f"(lo), "f"(hi));
    return d;
}
__device__ __forceinline__ void unpack2(unsigned long long v, float& lo, float& hi) {
    asm("mov.b64 {%0, %1}, %2;" : "=f"(lo), "=f"(hi) : "l"(v));
}

// Persistent kernel over the compacted winner list. One warp per winner.
// Lane = (cg, mg): cg = lane>>1 owns channels [4cg, 4cg+4)  (16 groups),
//                  mg = lane&1  owns m-points  [16mg, 16mg+16).
// Pillar x stored DUPLICATED (v,v) float2 in smem (padded rows, bank-shifted
// halves): inner loop = LDS.64 -> FFMA2, zero splat MOVs (round-6 core) at
// only 36 weight regs -> ~78 live regs -> 3 blocks/SM (24 warps, 1.5x r6).
// Double-buffered; next pillar register-staged (9 LDG/lane) during compute.
__global__ void __launch_bounds__(256, 3) k_compute(
    const float* __restrict__ pillars,
    const float* __restrict__ cw,
    const float* __restrict__ gamma,
    const float* __restrict__ beta,
    const float* __restrict__ mean,
    const float* __restrict__ var,
    float* __restrict__ out)
{
    __shared__ __align__(16) float2 sm[8][2][BUFSZ];
    const int wlocal = threadIdx.x >> 5;
    const int lane   = threadIdx.x & 31;
    const int cg     = lane >> 1;
    const int mg     = lane & 1;

    // Per-warp constants: wp[f][p] = (w[4cg+2p][f], w[4cg+2p+1][f])  (36 regs)
    unsigned long long wp[9][2];
    #pragma unroll
    for (int p = 0; p < 2; p++) {
        const float* w0 = cw + (cg * 4 + 2 * p) * 9;
        #pragma unroll
        for (int f = 0; f < 9; f++)
            wp[f][p] = pack2(w0[f], w0[9 + f]);
    }
    const int cs = cg * 4 + mg * 2;   // the 2 channels this lane stores
    const float s0 = gamma[cs]     * rsqrtf(var[cs]     + 1e-5f);
    const float s1 = gamma[cs + 1] * rsqrtf(var[cs + 1] + 1e-5f);
    const float b0 = beta[cs]     - mean[cs]     * s0;
    const float b1 = beta[cs + 1] - mean[cs + 1] * s1;

    const int count = g_count;
    const int w0id  = (blockIdx.x * blockDim.x + threadIdx.x) >> 5;
    int i = w0id;
    if (i >= count) return;

    // Stage pillar i into registers (9 floats/lane, coalesced: lane+32k)
    int2 eA = g_list[i];
    float xv[9];
    {
        const float* src = pillars + (size_t)eA.x * 288;
        #pragma unroll
        for (int k = 0; k < 9; k++) xv[k] = src[lane + 32 * k];
    }
    const int half = mg ? HALF : 0;   // this lane's m-half base (float2 units)
    int pb = 0;

    for (; i < count; i += NWARPS) {
        // Write current pillar, duplicated, into smem buffer pb.
        // pos(m,f) = m*ROW + f + (m>>4)  (the +1 gap bank-shifts the halves)
        float2* buf = sm[wlocal][pb];
        #pragma unroll
        for (int k = 0; k < 9; k++) {
            const int ii = lane + 32 * k;
            const int m  = ii / 9;
            const int f  = ii - 9 * m;
            buf[m * ROW + f + (m >> 4)] = make_float2(xv[k], xv[k]);
        }
        __syncwarp();

        // Prefetch next list entry + pillar into registers
        const int inext = i + NWARPS;
        int2 eB = g_list[(inext < count) ? inext : i];
        if (inext < count) {
            const float* src = pillars + (size_t)eB.x * 288;
            #pragma unroll
            for (int k = 0; k < 9; k++) xv[k] = src[lane + 32 * k];
        }

        // Compute: 4 channel maxes over this lane's 16 m-points
        float mx0 = -3.402823466e38f, mx1 = mx0, mx2 = mx0, mx3 = mx0;
        #pragma unroll
        for (int mi = 0; mi < 16; mi++) {
            const unsigned long long* xr =
                reinterpret_cast<const unsigned long long*>(buf + half + mi * ROW);
            unsigned long long a0 = 0ull, a1 = 0ull;
            #pragma unroll
            for (int f = 0; f < 9; f++) {
                const unsigned long long xs = xr[f];   // LDS.64: (x, x)
                a0 = fma2(xs, wp[f][0], a0);
                a1 = fma2(xs, wp[f][1], a1);
            }
            float lo, hi;
            unpack2(a0, lo, hi); mx0 = fmaxf(mx0, lo); mx1 = fmaxf(mx1, hi);
            unpack2(a1, lo, hi); mx2 = fmaxf(mx2, lo); mx3 = fmaxf(mx3, hi);
        }
        __syncwarp();   // all lanes done reading buf before it is refilled

        // Merge the two m-halves (partner lane = lane^1)
        mx0 = fmaxf(mx0, __shfl_xor_sync(0xFFFFFFFFu, mx0, 1));
        mx1 = fmaxf(mx1, __shfl_xor_sync(0xFFFFFFFFu, mx1, 1));
        mx2 = fmaxf(mx2, __shfl_xor_sync(0xFFFFFFFFu, mx2, 1));
        mx3 = fmaxf(mx3, __shfl_xor_sync(0xFFFFFFFFu, mx3, 1));

        // BN+ReLU once on the raw max (scale>0, monotone => exact)
        const float ra = mg ? mx2 : mx0;
        const float rb = mg ? mx3 : mx1;
        const float fA = fmaxf(fmaf(ra, s0, b0), 0.0f);
        const float fB = fmaxf(fmaf(rb, s1, b1), 0.0f);
        const size_t base = (size_t)eA.y + (size_t)cs * CELLS;
        out[base]         = fA;
        out[base + CELLS] = fB;

        eA = eB;
        pb ^= 1;
    }
}

extern "C" void kernel_launch(void* const* d_in, const int* in_sizes, int n_in,
                              void* d_out, int out_size) {
    const float* pillars = (const float*)d_in[0];
    const int*   idx     = (const int*)d_in[1];
    const float* cw      = (const float*)d_in[2];
    const float* gamma   = (const float*)d_in[3];
    const float* beta    = (const float*)d_in[4];
    const float* mean    = (const float*)d_in[5];
    const float* var     = (const float*)d_in[6];
    float* out = (float*)d_out;

    void *winner_ptr = nullptr, *count_ptr = nullptr;
    cudaGetSymbolAddress(&winner_ptr, g_winner);
    cudaGetSymbolAddress(&count_ptr, g_count);

    cudaMemsetAsync(out, 0, (size_t)out_size * sizeof(float), 0);
    cudaMemsetAsync(winner_ptr, 0xFF, sizeof(int) * NC, 0);  // -1
    cudaMemsetAsync(count_ptr, 0, sizeof(int), 0);
    k_winner<<<NP / 256, 256>>>(idx);
    k_collect<<<NP / 256, 256>>>(idx);
    k_compute<<<NBLK, 256>>>(pillars, cw, gamma, beta, mean, var, out);
}